// round 6
// baseline (speedup 1.0000x reference)
#include <cuda_runtime.h>

// DotAttention: rnn_out [S,B,H] f32, state [2,2,B,H/2] f32 -> out [B,H,1] f32
// S=2048, B=32, H=1024.
// pass1: flash-style online-softmax partials; one warp per (b, 32-row chunk).
//        cp.async double-buffered row staging in smem (per-thread groups, no
//        barriers), merged vector register-resident. 512 CTAs x 128 thr =
//        one wave at 4 CTAs/SM.
// pass2: fused combine (M/L) + weighted sum, 256 CTAs, MLP=8.

#define S_LEN 2048
#define B_DIM 32
#define H_DIM 1024
#define SPLIT 64
#define CHUNK (S_LEN / SPLIT)          // 32 rows per warp
#define NPART (B_DIM * SPLIT)          // 2048 partials

__device__ float g_m[NPART];
__device__ float g_l[NPART];
__device__ float g_acc[(size_t)NPART * H_DIM];   // 8.4 MB scratch (L2-resident)

__device__ __forceinline__ unsigned smem_u32(const void* p) {
    return (unsigned)__cvta_generic_to_shared(p);
}

__global__ __launch_bounds__(128, 4) void pass1(const float* __restrict__ rnn,
                                                const float* __restrict__ state) {
    // [warp][stage][8*32 float4] = 4 * 2 * 4KB = 32KB
    __shared__ float4 buf[4][2][256];

    const int lane = threadIdx.x & 31;
    const int wid  = threadIdx.x >> 5;           // 0..3
    const int warp = blockIdx.x * 4 + wid;
    const int b     = warp >> 6;                 // /SPLIT
    const int chunk = warp & 63;                 // %SPLIT

    // merged[b, h]: h = j*128 + lane*4; direction = h>>9
    float4 mrg[8];
#pragma unroll
    for (int j = 0; j < 8; j++) {
        int h = j * 128 + lane * 4;
        int d = h >> 9;
        int hh = h & 511;
        mrg[j] = *reinterpret_cast<const float4*>(
            state + (size_t)(2 + d) * B_DIM * 512 + (size_t)b * 512 + hh);
    }

    float4 acc[8];
#pragma unroll
    for (int j = 0; j < 8; j++) acc[j] = make_float4(0.f, 0.f, 0.f, 0.f);
    float m = -1e30f, l = 0.f;

    const float* base = rnn + (size_t)(chunk * CHUNK) * (B_DIM * H_DIM)
                            + (size_t)b * H_DIM;

    // issue row s into stage st (this thread loads exactly what it consumes)
    auto issue = [&](int s, int st) {
        const float4* row =
            reinterpret_cast<const float4*>(base + (size_t)s * (B_DIM * H_DIM));
#pragma unroll
        for (int j = 0; j < 8; j++) {
            unsigned dst = smem_u32(&buf[wid][st][j * 32 + lane]);
            const float4* src = &row[j * 32 + lane];
            asm volatile("cp.async.cg.shared.global [%0], [%1], 16;\n"
                         :: "r"(dst), "l"(src));
        }
        asm volatile("cp.async.commit_group;\n");
    };

    issue(0, 0);
    issue(1, 1);

    for (int s = 0; s < CHUNK; s++) {
        const int st = s & 1;
        if (s + 1 < CHUNK)
            asm volatile("cp.async.wait_group 1;\n");
        else
            asm volatile("cp.async.wait_group 0;\n");

        float4 x[8];
#pragma unroll
        for (int j = 0; j < 8; j++) x[j] = buf[wid][st][j * 32 + lane];

        // start the next load while computing
        if (s + 2 < CHUNK) issue(s + 2, st);

        float p = 0.f;
#pragma unroll
        for (int j = 0; j < 8; j++) {
            p += x[j].x * mrg[j].x + x[j].y * mrg[j].y +
                 x[j].z * mrg[j].z + x[j].w * mrg[j].w;
        }
#pragma unroll
        for (int off = 16; off > 0; off >>= 1)
            p += __shfl_xor_sync(0xffffffffu, p, off);

        float mnew  = fmaxf(m, p);
        float scale = __expf(m - mnew);
        float w     = __expf(p - mnew);
#pragma unroll
        for (int j = 0; j < 8; j++) {
            acc[j].x = acc[j].x * scale + w * x[j].x;
            acc[j].y = acc[j].y * scale + w * x[j].y;
            acc[j].z = acc[j].z * scale + w * x[j].z;
            acc[j].w = acc[j].w * scale + w * x[j].w;
        }
        l = l * scale + w;
        m = mnew;
    }

    float4* out4 = reinterpret_cast<float4*>(g_acc + (size_t)warp * H_DIM);
#pragma unroll
    for (int j = 0; j < 8; j++) out4[j * 32 + lane] = acc[j];
    if (lane == 0) {
        g_m[warp] = m;
        g_l[warp] = l;
    }
}

// Fused combine + weighted sum. grid = (8 h-slices, 32 batches), 256 threads.
// Each CTA covers 128 h values; each thread sums 8 chunks (MLP=8).
__global__ __launch_bounds__(256) void pass2(float* __restrict__ out) {
    const int slice = blockIdx.x;        // 0..7  (128 h each)
    const int b     = blockIdx.y;        // 0..31
    const int tid   = threadIdx.x;
    const int lane  = tid & 31;
    const int wid   = tid >> 5;

    __shared__ float sw[SPLIT];
    __shared__ float s_red[8];

    // ---- normalized chunk weights (threads 0..SPLIT-1 own one chunk) ----
    float mm = -1e30f, ll = 0.f;
    if (tid < SPLIT) {
        mm = g_m[b * SPLIT + tid];
        ll = g_l[b * SPLIT + tid];
    }
    float v = mm;
#pragma unroll
    for (int off = 16; off > 0; off >>= 1)
        v = fmaxf(v, __shfl_xor_sync(0xffffffffu, v, off));
    if (lane == 0) s_red[wid] = v;
    __syncthreads();
    float M = s_red[0];
#pragma unroll
    for (int k = 1; k < 8; k++) M = fmaxf(M, s_red[k]);
    __syncthreads();

    float e  = (tid < SPLIT) ? __expf(mm - M) : 0.f;
    float le = ll * e;
#pragma unroll
    for (int off = 16; off > 0; off >>= 1)
        le += __shfl_xor_sync(0xffffffffu, le, off);
    if (lane == 0) s_red[wid] = le;
    __syncthreads();
    float L = 0.f;
#pragma unroll
    for (int k = 0; k < 8; k++) L += s_red[k];
    if (tid < SPLIT) sw[tid] = e / L;
    __syncthreads();

    // ---- weighted sum over SPLIT chunks for 128 h values ----
    const int hq = tid & 31;             // 32 float4 = 128 floats per slice
    const int cg = tid >> 5;             // 8 groups x 8 chunks

    const float* bse = g_acc + ((size_t)b * SPLIT) * H_DIM + slice * 128 + hq * 4;

    float rx = 0.f, ry = 0.f, rz = 0.f, rw = 0.f;
#pragma unroll
    for (int k = 0; k < 8; k++) {
        int chunk = k * 8 + cg;
        float4 a = *reinterpret_cast<const float4*>(bse + (size_t)chunk * H_DIM);
        float w = sw[chunk];
        rx += w * a.x; ry += w * a.y; rz += w * a.z; rw += w * a.w;
    }

    __shared__ float4 red[256];
    red[tid] = make_float4(rx, ry, rz, rw);
    __syncthreads();
#pragma unroll
    for (int st = 4; st > 0; st >>= 1) {
        if (cg < st) {
            float4 o = red[tid + 32 * st];
            rx += o.x; ry += o.y; rz += o.z; rw += o.w;
            red[tid] = make_float4(rx, ry, rz, rw);
        }
        __syncthreads();
    }

    if (cg == 0) {
        reinterpret_cast<float4*>(out)[(b * H_DIM + slice * 128) / 4 + hq] =
            make_float4(rx, ry, rz, rw);
    }
}

extern "C" void kernel_launch(void* const* d_in, const int* in_sizes, int n_in,
                              void* d_out, int out_size) {
    const float* rnn   = (const float*)d_in[0];
    const float* state = (const float*)d_in[1];
    float* out         = (float*)d_out;

    pass1<<<NPART / 4, 128>>>(rnn, state);
    dim3 g2(8, B_DIM);
    pass2<<<g2, 256>>>(out);
}

// round 7
// speedup vs baseline: 1.0477x; 1.0477x over previous
#include <cuda_runtime.h>

// DotAttention: rnn_out [S,B,H] f32, state [2,2,B,H/2] f32 -> out [B,H,1] f32
// S=2048, B=32, H=1024.
// pass1: flash-style online-softmax partials; one warp per (b, 32-row chunk),
//        register-resident merged vector; 8 warps/CTA combine their partials
//        in smem -> one partial per CTA (NPART=256, scratch 1MB).
// pass2: tiny fused combine + weighted sum over 8 partials/batch, 32 CTAs.

#define S_LEN 2048
#define B_DIM 32
#define H_DIM 1024
#define SPLIT 64
#define CHUNK (S_LEN / SPLIT)          // 32 rows per warp
#define WARPS_PER_CTA 8
#define NCTA  (B_DIM * SPLIT / WARPS_PER_CTA)   // 256 CTAs, one partial each
#define PPB   (SPLIT / WARPS_PER_CTA)           // 8 partials per batch

__device__ float g_m[NCTA];
__device__ float g_l[NCTA];
__device__ float g_acc[(size_t)NCTA * H_DIM];   // 1 MB scratch (L2-resident)

__global__ __launch_bounds__(256) void pass1(const float* __restrict__ rnn,
                                             const float* __restrict__ state) {
    const int tid  = threadIdx.x;
    const int lane = tid & 31;
    const int wid  = tid >> 5;
    const int warp  = blockIdx.x * WARPS_PER_CTA + wid;
    const int b     = warp / SPLIT;
    const int chunk = warp % SPLIT;

    // merged[b, h]: h = j*128 + lane*4; direction = h>>9
    float4 mrg[8];
#pragma unroll
    for (int j = 0; j < 8; j++) {
        int h = j * 128 + lane * 4;
        int d = h >> 9;
        int hh = h & 511;
        mrg[j] = *reinterpret_cast<const float4*>(
            state + (size_t)(2 + d) * B_DIM * 512 + (size_t)b * 512 + hh);
    }

    float4 acc[8];
#pragma unroll
    for (int j = 0; j < 8; j++) acc[j] = make_float4(0.f, 0.f, 0.f, 0.f);
    float m = -1e30f, l = 0.f;

    const float* base = rnn + (size_t)(chunk * CHUNK) * (B_DIM * H_DIM)
                            + (size_t)b * H_DIM;

    for (int s = 0; s < CHUNK; s++) {
        const float4* row =
            reinterpret_cast<const float4*>(base + (size_t)s * (B_DIM * H_DIM));
        float4 x[8];
#pragma unroll
        for (int j = 0; j < 8; j++) x[j] = row[j * 32 + lane];

        float p = 0.f;
#pragma unroll
        for (int j = 0; j < 8; j++) {
            p += x[j].x * mrg[j].x + x[j].y * mrg[j].y +
                 x[j].z * mrg[j].z + x[j].w * mrg[j].w;
        }
#pragma unroll
        for (int off = 16; off > 0; off >>= 1)
            p += __shfl_xor_sync(0xffffffffu, p, off);

        float mnew  = fmaxf(m, p);
        float scale = __expf(m - mnew);
        float w     = __expf(p - mnew);
#pragma unroll
        for (int j = 0; j < 8; j++) {
            acc[j].x = acc[j].x * scale + w * x[j].x;
            acc[j].y = acc[j].y * scale + w * x[j].y;
            acc[j].z = acc[j].z * scale + w * x[j].z;
            acc[j].w = acc[j].w * scale + w * x[j].w;
        }
        l = l * scale + w;
        m = mnew;
    }

    // ---- CTA-level combine of the 8 warps' partials ----
    __shared__ float s_m[WARPS_PER_CTA], s_l[WARPS_PER_CTA];
    __shared__ float4 sbuf[WARPS_PER_CTA][H_DIM / 4 / WARPS_PER_CTA * 8]; // [8][256] = 32KB

    if (lane == 0) { s_m[wid] = m; s_l[wid] = l; }
    __syncthreads();

    float M = s_m[0];
#pragma unroll
    for (int k = 1; k < WARPS_PER_CTA; k++) M = fmaxf(M, s_m[k]);
    float sc = __expf(m - M);

#pragma unroll
    for (int j = 0; j < 8; j++) {
        sbuf[wid][j * 32 + lane] =
            make_float4(acc[j].x * sc, acc[j].y * sc, acc[j].z * sc, acc[j].w * sc);
    }
    __syncthreads();

    // warp `wid` reduces j-group `wid` across the 8 staged buffers
    float4 r = make_float4(0.f, 0.f, 0.f, 0.f);
#pragma unroll
    for (int k = 0; k < WARPS_PER_CTA; k++) {
        float4 a = sbuf[k][wid * 32 + lane];
        r.x += a.x; r.y += a.y; r.z += a.z; r.w += a.w;
    }

    float4* out4 = reinterpret_cast<float4*>(g_acc + (size_t)blockIdx.x * H_DIM);
    out4[wid * 32 + lane] = r;

    if (tid == 0) {
        float L = 0.f;
#pragma unroll
        for (int k = 0; k < WARPS_PER_CTA; k++)
            L += s_l[k] * __expf(s_m[k] - M);
        g_m[blockIdx.x] = M;
        g_l[blockIdx.x] = L;
    }
}

// Combine + weighted sum over PPB=8 partials per batch. grid = 32 CTAs.
__global__ __launch_bounds__(256) void pass2(float* __restrict__ out) {
    const int b   = blockIdx.x;
    const int tid = threadIdx.x;         // owns one float4 (256*4 = 1024 = H)

    // per-thread redundant weight computation (8 pairs, L1/L2-broadcast)
    float mv[PPB], lv[PPB];
#pragma unroll
    for (int k = 0; k < PPB; k++) {
        mv[k] = g_m[b * PPB + k];
        lv[k] = g_l[b * PPB + k];
    }
    float M = mv[0];
#pragma unroll
    for (int k = 1; k < PPB; k++) M = fmaxf(M, mv[k]);
    float L = 0.f;
    float w[PPB];
#pragma unroll
    for (int k = 0; k < PPB; k++) {
        w[k] = __expf(mv[k] - M);
        L += lv[k] * w[k];
    }
    float inv = 1.f / L;

    const float* bse = g_acc + ((size_t)b * PPB) * H_DIM + tid * 4;
    float rx = 0.f, ry = 0.f, rz = 0.f, rw = 0.f;
#pragma unroll
    for (int k = 0; k < PPB; k++) {
        float4 a = *reinterpret_cast<const float4*>(bse + (size_t)k * H_DIM);
        rx += w[k] * a.x; ry += w[k] * a.y; rz += w[k] * a.z; rw += w[k] * a.w;
    }
    reinterpret_cast<float4*>(out)[b * (H_DIM / 4) + tid] =
        make_float4(rx * inv, ry * inv, rz * inv, rw * inv);
}

extern "C" void kernel_launch(void* const* d_in, const int* in_sizes, int n_in,
                              void* d_out, int out_size) {
    const float* rnn   = (const float*)d_in[0];
    const float* state = (const float*)d_in[1];
    float* out         = (float*)d_out;

    pass1<<<NCTA, 256>>>(rnn, state);
    pass2<<<B_DIM, 256>>>(out);
}

// round 8
// speedup vs baseline: 1.0484x; 1.0007x over previous
#include <cuda_runtime.h>

// DotAttention: rnn_out [S,B,H] f32, state [2,2,B,H/2] f32 -> out [B,H,1] f32
// S=2048, B=32, H=1024.
// Single kernel: flash-style online-softmax partials (one warp per 32-row
// chunk, 8 warps/CTA combine in smem -> one partial per CTA), then the LAST
// CTA of each batch (atomic counter) combines the batch's 8 partials and
// writes the final output. No second launch.

#define S_LEN 2048
#define B_DIM 32
#define H_DIM 1024
#define SPLIT 64
#define CHUNK (S_LEN / SPLIT)          // 32 rows per warp
#define WARPS_PER_CTA 8
#define NCTA  (B_DIM * SPLIT / WARPS_PER_CTA)   // 256 CTAs
#define PPB   (SPLIT / WARPS_PER_CTA)           // 8 CTAs (partials) per batch

__device__ float g_m[NCTA];
__device__ float g_l[NCTA];
__device__ float g_acc[(size_t)NCTA * H_DIM];   // 1 MB scratch (L2-resident)
__device__ unsigned g_cnt[B_DIM];               // zero-init; reset each run

__global__ __launch_bounds__(256) void pass1(const float* __restrict__ rnn,
                                             const float* __restrict__ state,
                                             float* __restrict__ out) {
    const int tid  = threadIdx.x;
    const int lane = tid & 31;
    const int wid  = tid >> 5;
    const int warp  = blockIdx.x * WARPS_PER_CTA + wid;
    const int b     = warp / SPLIT;
    const int chunk = warp % SPLIT;

    // merged[b, h]: h = j*128 + lane*4; direction = h>>9
    float4 mrg[8];
#pragma unroll
    for (int j = 0; j < 8; j++) {
        int h = j * 128 + lane * 4;
        int d = h >> 9;
        int hh = h & 511;
        mrg[j] = *reinterpret_cast<const float4*>(
            state + (size_t)(2 + d) * B_DIM * 512 + (size_t)b * 512 + hh);
    }

    float4 acc[8];
#pragma unroll
    for (int j = 0; j < 8; j++) acc[j] = make_float4(0.f, 0.f, 0.f, 0.f);
    float m = -1e30f, l = 0.f;

    const float* base = rnn + (size_t)(chunk * CHUNK) * (B_DIM * H_DIM)
                            + (size_t)b * H_DIM;

    for (int s = 0; s < CHUNK; s++) {
        const float4* row =
            reinterpret_cast<const float4*>(base + (size_t)s * (B_DIM * H_DIM));
        float4 x[8];
#pragma unroll
        for (int j = 0; j < 8; j++) x[j] = row[j * 32 + lane];

        float p = 0.f;
#pragma unroll
        for (int j = 0; j < 8; j++) {
            p += x[j].x * mrg[j].x + x[j].y * mrg[j].y +
                 x[j].z * mrg[j].z + x[j].w * mrg[j].w;
        }
#pragma unroll
        for (int off = 16; off > 0; off >>= 1)
            p += __shfl_xor_sync(0xffffffffu, p, off);

        float mnew  = fmaxf(m, p);
        float scale = __expf(m - mnew);
        float w     = __expf(p - mnew);
#pragma unroll
        for (int j = 0; j < 8; j++) {
            acc[j].x = acc[j].x * scale + w * x[j].x;
            acc[j].y = acc[j].y * scale + w * x[j].y;
            acc[j].z = acc[j].z * scale + w * x[j].z;
            acc[j].w = acc[j].w * scale + w * x[j].w;
        }
        l = l * scale + w;
        m = mnew;
    }

    // ---- CTA-level combine of the 8 warps' partials ----
    __shared__ float s_m[WARPS_PER_CTA], s_l[WARPS_PER_CTA];
    __shared__ float4 sbuf[WARPS_PER_CTA][256];   // 32 KB
    __shared__ unsigned s_last;

    if (lane == 0) { s_m[wid] = m; s_l[wid] = l; }
    __syncthreads();

    float M = s_m[0];
#pragma unroll
    for (int k = 1; k < WARPS_PER_CTA; k++) M = fmaxf(M, s_m[k]);
    float sc = __expf(m - M);

#pragma unroll
    for (int j = 0; j < 8; j++) {
        sbuf[wid][j * 32 + lane] =
            make_float4(acc[j].x * sc, acc[j].y * sc, acc[j].z * sc, acc[j].w * sc);
    }
    __syncthreads();

    // warp `wid` reduces j-group `wid` across the 8 staged buffers
    float4 r = make_float4(0.f, 0.f, 0.f, 0.f);
#pragma unroll
    for (int k = 0; k < WARPS_PER_CTA; k++) {
        float4 a = sbuf[k][wid * 32 + lane];
        r.x += a.x; r.y += a.y; r.z += a.z; r.w += a.w;
    }

    float4* out4 = reinterpret_cast<float4*>(g_acc + (size_t)blockIdx.x * H_DIM);
    out4[wid * 32 + lane] = r;

    if (tid == 0) {
        float L = 0.f;
#pragma unroll
        for (int k = 0; k < WARPS_PER_CTA; k++)
            L += s_l[k] * __expf(s_m[k] - M);
        g_m[blockIdx.x] = M;
        g_l[blockIdx.x] = L;
    }

    // ---- last CTA of this batch combines the batch's PPB partials ----
    __threadfence();
    __syncthreads();
    if (tid == 0) {
        unsigned old = atomicAdd(&g_cnt[b], 1u);
        s_last = (old == PPB - 1) ? 1u : 0u;
    }
    __syncthreads();
    if (!s_last) return;

    __threadfence();   // acquire: make other CTAs' g_acc/g_m/g_l visible

    float mv[PPB], lv[PPB];
#pragma unroll
    for (int k = 0; k < PPB; k++) {
        mv[k] = g_m[b * PPB + k];
        lv[k] = g_l[b * PPB + k];
    }
    float Mf = mv[0];
#pragma unroll
    for (int k = 1; k < PPB; k++) Mf = fmaxf(Mf, mv[k]);
    float Lf = 0.f;
    float w[PPB];
#pragma unroll
    for (int k = 0; k < PPB; k++) {
        w[k] = __expf(mv[k] - Mf);
        Lf += lv[k] * w[k];
    }
    float inv = 1.f / Lf;

    const float* bse = g_acc + ((size_t)b * PPB) * H_DIM + tid * 4;
    float rx = 0.f, ry = 0.f, rz = 0.f, rw = 0.f;
#pragma unroll
    for (int k = 0; k < PPB; k++) {
        float4 a = *reinterpret_cast<const float4*>(bse + (size_t)k * H_DIM);
        rx += w[k] * a.x; ry += w[k] * a.y; rz += w[k] * a.z; rw += w[k] * a.w;
    }
    reinterpret_cast<float4*>(out)[b * (H_DIM / 4) + tid] =
        make_float4(rx * inv, ry * inv, rz * inv, rw * inv);

    if (tid == 0) g_cnt[b] = 0;   // reset for next run / graph replay
}

extern "C" void kernel_launch(void* const* d_in, const int* in_sizes, int n_in,
                              void* d_out, int out_size) {
    const float* rnn   = (const float*)d_in[0];
    const float* state = (const float*)d_in[1];
    float* out         = (float*)d_out;

    pass1<<<NCTA, 256>>>(rnn, state, out);
}